// round 15
// baseline (speedup 1.0000x reference)
#include <cuda_runtime.h>
#include <cuda_fp16.h>
#include <cstdint>

#define NTOK 512
#define CDIM 128
#define LLOC 144
#define DDIM 256
#define FSTRIDE (LLOC * CDIM)
#define SKB 272                   // smem row stride (bytes, 136 halves)
#define PKB 528                   // setup GEMM smem row stride
#define LOG2E 1.4426950408889634f
#define LN2   0.6931471805599453f
#define FMAPN (NTOK * LLOC * CDIM)
#define CONVB (FMAPN / 2048)

// main_k smem byte offsets
#define OFF_A2   0                // loc -> preds2 tile, 128*272 = 34816
#define OFF_B0   34816            // 3 pos buffers, 64*272 = 17408 each
#define BBUF_SZ  17408
#define OFF_ROWS 87040            // 256 floats
#define OFF_WRED 88064            // 8 floats
#define SMEM_TOTAL 88096          // x2 = 176KB -> 2 CTAs/SM
// setup_k smem
#define P_OFF_B  67584
#define P_SMEM   101376

__device__ __half g_posh[FMAPN];            // fmap_tp1, fp16
__device__ uint4  g_p1f[4 * 4 * 2 * 8 * 32];// preds1*log2e in ldmatrix-fragment order
__device__ double g_acc;
__device__ unsigned int g_done;

__device__ __forceinline__ uint32_t ph2(float x, float y) {
    __half2 h = __floats2half2_rn(x, y);
    return *reinterpret_cast<uint32_t*>(&h);
}
__device__ __forceinline__ float2 up2(uint32_t v) {
    return __half22float2(*reinterpret_cast<__half2*>(&v));
}
__device__ __forceinline__ float ex2f(float x) {
    float r; asm("ex2.approx.f32 %0, %1;" : "=f"(r) : "f"(x)); return r;
}
__device__ __forceinline__ void cpa16(uint32_t dst, const void* src) {
    asm volatile("cp.async.cg.shared.global [%0], [%1], 16;"
                 :: "r"(dst), "l"(src) : "memory");
}
#define CP_COMMIT() asm volatile("cp.async.commit_group;" ::: "memory")
#define CP_WAIT(n)  asm volatile("cp.async.wait_group %0;" :: "n"(n) : "memory")

__device__ __forceinline__ void stage8h(char* tile, int row, int k0,
                                        const float* __restrict__ src) {
    float4 a = *reinterpret_cast<const float4*>(src);
    float4 b = *reinterpret_cast<const float4*>(src + 4);
    uint4 v;
    v.x = ph2(a.x, a.y); v.y = ph2(a.z, a.w);
    v.z = ph2(b.x, b.y); v.w = ph2(b.z, b.w);
    *reinterpret_cast<uint4*>(tile + row * SKB + k0 * 2) = v;
}
__device__ __forceinline__ void stage8hs(char* tile, int row, int k0,
                                         const float* __restrict__ src, float s) {
    float4 a = *reinterpret_cast<const float4*>(src);
    float4 b = *reinterpret_cast<const float4*>(src + 4);
    uint4 v;
    v.x = ph2(a.x * s, a.y * s); v.y = ph2(a.z * s, a.w * s);
    v.z = ph2(b.x * s, b.y * s); v.w = ph2(b.z * s, b.w * s);
    *reinterpret_cast<uint4*>(tile + row * SKB + k0 * 2) = v;
}

#define LDSM4(r0, r1, r2, r3, addr) \
    asm volatile("ldmatrix.sync.aligned.m8n8.x4.shared.b16 {%0,%1,%2,%3}, [%4];" \
                 : "=r"(r0), "=r"(r1), "=r"(r2), "=r"(r3) : "r"(addr))

__device__ __forceinline__ void mma16h(uint32_t* c, const uint32_t* a, const uint32_t* b) {
    asm volatile(
        "mma.sync.aligned.m16n8k16.row.col.f16.f16.f16.f16 "
        "{%0,%1}, {%2,%3,%4,%5}, {%6,%7}, {%0,%1};\n"
        : "+r"(c[0]), "+r"(c[1])
        : "r"(a[0]), "r"(a[1]), "r"(a[2]), "r"(a[3]), "r"(b[0]), "r"(b[1]));
}
__device__ __forceinline__ void mma16f(float* c, const uint32_t* a, const uint32_t* b) {
    asm volatile(
        "mma.sync.aligned.m16n8k16.row.col.f32.f16.f16.f32 "
        "{%0,%1,%2,%3}, {%4,%5,%6,%7}, {%8,%9}, {%0,%1,%2,%3};\n"
        : "+f"(c[0]), "+f"(c[1]), "+f"(c[2]), "+f"(c[3])
        : "r"(a[0]), "r"(a[1]), "r"(a[2]), "r"(a[3]), "r"(b[0]), "r"(b[1]));
}

// ---- setup: blocks 0-7 = preds1 GEMM (frag-order output); blocks 8.. = pos cvt ----
__global__ void __launch_bounds__(256, 2)
setup_k(const float* __restrict__ f_t,
        const float* __restrict__ W1,
        const float* __restrict__ b1,
        const float* __restrict__ fmap_tp1) {
    const int t = threadIdx.x;
    if (blockIdx.x >= 8) {
        size_t i = ((size_t)(blockIdx.x - 8) * 256 + t) * 8;
        float4 a = *reinterpret_cast<const float4*>(fmap_tp1 + i);
        float4 b = *reinterpret_cast<const float4*>(fmap_tp1 + i + 4);
        uint4 v;
        v.x = ph2(a.x, a.y); v.y = ph2(a.z, a.w);
        v.z = ph2(b.x, b.y); v.w = ph2(b.z, b.w);
        *reinterpret_cast<uint4*>(g_posh + i) = v;
        return;
    }

    extern __shared__ char psm[];
    const uint32_t sb = (uint32_t)__cvta_generic_to_shared(psm);
    const int nb = blockIdx.x & 3, nh = blockIdx.x >> 2;
    const int lane = t & 31, warp = t >> 5;
    const int wy = warp >> 1, wx = warp & 1;
    if (blockIdx.x == 0 && t == 0) g_acc = 0.0;

    {   // stage A rows (f_t slab)
        int row = t >> 1, half = t & 1;
        const float4* sa = reinterpret_cast<const float4*>(
            f_t + (size_t)(nb * 128 + row) * DDIM + half * 128);
        uint2* da = reinterpret_cast<uint2*>(psm + row * PKB + half * 256);
#pragma unroll
        for (int j = 0; j < 32; ++j) {
            float4 a = sa[j];
            da[j] = make_uint2(ph2(a.x, a.y), ph2(a.z, a.w));
        }
    }
    {   // stage B rows (W1 slice, 64 rows)
        int row = t >> 2, q = t & 3;
        const float4* sw = reinterpret_cast<const float4*>(
            W1 + (size_t)(nh * 64 + row) * DDIM + q * 64);
        uint2* dw = reinterpret_cast<uint2*>(psm + P_OFF_B + row * PKB + q * 128);
#pragma unroll
        for (int j = 0; j < 16; ++j) {
            float4 w = sw[j];
            dw[j] = make_uint2(ph2(w.x, w.y), ph2(w.z, w.w));
        }
    }
    __syncthreads();

    const uint32_t aRow = lane & 15, aKoff = ((lane >> 4) << 3);
    const uint32_t bRow = ((lane >> 4) << 3) + (lane & 7), bKoff = (((lane >> 3) & 1) << 3);
    const int g = lane >> 2, tig = lane & 3;

    float pc[2][4][4];
#pragma unroll
    for (int mi = 0; mi < 2; ++mi)
#pragma unroll
        for (int ni = 0; ni < 4; ++ni)
#pragma unroll
            for (int q = 0; q < 4; ++q) pc[mi][ni][q] = 0.f;

#pragma unroll 2
    for (int ks = 0; ks < 16; ++ks) {
        const int k0 = ks * 16;
        uint32_t a[2][4], b[4][2];
#pragma unroll
        for (int mi = 0; mi < 2; ++mi) {
            uint32_t ad = sb + (wy * 32 + mi * 16 + aRow) * PKB + (k0 + aKoff) * 2;
            LDSM4(a[mi][0], a[mi][1], a[mi][2], a[mi][3], ad);
        }
#pragma unroll
        for (int nt = 0; nt < 2; ++nt) {
            uint32_t bd = sb + P_OFF_B + (wx * 32 + nt * 16 + bRow) * PKB + (k0 + bKoff) * 2;
            LDSM4(b[nt * 2][0], b[nt * 2][1], b[nt * 2 + 1][0], b[nt * 2 + 1][1], bd);
        }
#pragma unroll
        for (int mi = 0; mi < 2; ++mi)
#pragma unroll
            for (int ni = 0; ni < 4; ++ni) mma16f(pc[mi][ni], a[mi], b[ni]);
    }

    // write preds1*log2e in fragment order: uint4 index (((nb*4+wy)*2+mi)*8+ks2)*32+lane
#pragma unroll
    for (int mi = 0; mi < 2; ++mi)
#pragma unroll
        for (int ni = 0; ni < 4; ++ni) {
            int col = nh * 64 + wx * 32 + ni * 8 + tig * 2;
            int ks2 = col >> 4;              // = nh*4 + wx*2 + (ni>>1)
            float bv0 = __ldg(b1 + col), bv1 = __ldg(b1 + col + 1);
            size_t fidx = ((((size_t)(nb * 4 + wy) * 2 + mi) * 8 + ks2) * 32 + lane);
            uint32_t* fp = reinterpret_cast<uint32_t*>(g_p1f) + fidx * 4 + (ni & 1) * 2;
            fp[0] = ph2((pc[mi][ni][0] + bv0) * LOG2E, (pc[mi][ni][1] + bv1) * LOG2E);
            fp[1] = ph2((pc[mi][ni][2] + bv0) * LOG2E, (pc[mi][ni][3] + bv1) * LOG2E);
        }
}

__global__ void __launch_bounds__(256, 2)
main_k(const float* __restrict__ fmap_t,
       const float* __restrict__ W2,
       const float* __restrict__ b2,
       float* __restrict__ out) {
    extern __shared__ char sm[];
    const uint32_t sbase = (uint32_t)__cvta_generic_to_shared(sm);
    const uint32_t sbA2 = sbase + OFF_A2;
    float* rowS = reinterpret_cast<float*>(sm + OFF_ROWS);
    float* wred = reinterpret_cast<float*>(sm + OFF_WRED);

    const int l    = blockIdx.y;
    const int nb   = blockIdx.x;
    const int t    = threadIdx.x;
    const int lane = t & 31, warp = t >> 5;
    const int wy   = warp >> 1, wx = warp & 1;
    const int g    = lane >> 2, tig = lane & 3;

    const uint32_t aRow  = lane & 15;
    const uint32_t aKoff = ((lane >> 4) << 3);
    const uint32_t bRow  = ((lane >> 4) << 3) + (lane & 7);
    const uint32_t bKoff = (((lane >> 3) & 1) << 3);

    // per-thread base of A1 fragments (loop-invariant): + (mi*8 + ks)*32
    const uint4* pA1 = g_p1f + ((size_t)(nb * 4 + wy) * 2) * 8 * 32 + lane;

    // ---- Phase 0: loc fp32->fp16 into A2; W2*log2e into B0/B1 ----
#pragma unroll
    for (int j = 0; j < 8; ++j) {
        int idx = j * 256 + t, row = idx >> 4, k0 = (idx & 15) * 8;
        stage8h(sm + OFF_A2, row, k0,
                fmap_t + (size_t)(nb * 128 + row) * FSTRIDE + l * CDIM + k0);
    }
    {
        int row = t >> 2, k0 = (t & 3) * 32;
#pragma unroll
        for (int j = 0; j < 4; ++j) {
            stage8hs(sm + OFF_B0, row, k0 + j * 8,
                     W2 + (size_t)row * CDIM + k0 + j * 8, LOG2E);
            stage8hs(sm + OFF_B0 + BBUF_SZ, row, k0 + j * 8,
                     W2 + (size_t)(64 + row) * CDIM + k0 + j * 8, LOG2E);
        }
    }
    rowS[t] = 0.f;
    __syncthreads();

    // ---- Phase 1: preds2*log2e = loc @ (W2*log2e)^T ----
    uint32_t pc[2][2][4][2];
#pragma unroll
    for (int p = 0; p < 2; ++p)
#pragma unroll
        for (int mi = 0; mi < 2; ++mi)
#pragma unroll
            for (int ni = 0; ni < 4; ++ni) { pc[p][mi][ni][0] = 0u; pc[p][mi][ni][1] = 0u; }

#pragma unroll 1
    for (int p = 0; p < 2; ++p) {
        const uint32_t sbB = sbase + OFF_B0 + p * BBUF_SZ;
#pragma unroll
        for (int ks = 0; ks < 8; ++ks) {
            const int k0 = ks * 16;
            uint32_t a[2][4], b[4][2];
#pragma unroll
            for (int mi = 0; mi < 2; ++mi) {
                uint32_t ad = sbA2 + (wy * 32 + mi * 16 + aRow) * SKB + (k0 + aKoff) * 2;
                LDSM4(a[mi][0], a[mi][1], a[mi][2], a[mi][3], ad);
            }
#pragma unroll
            for (int nt = 0; nt < 2; ++nt) {
                uint32_t bd = sbB + (wx * 32 + nt * 16 + bRow) * SKB + (k0 + bKoff) * 2;
                LDSM4(b[nt * 2][0], b[nt * 2][1], b[nt * 2 + 1][0], b[nt * 2 + 1][1], bd);
            }
#pragma unroll
            for (int mi = 0; mi < 2; ++mi)
#pragma unroll
                for (int ni = 0; ni < 4; ++ni) mma16h(pc[p][mi][ni], a[mi], b[ni]);
        }
    }
    __syncthreads();                      // all reads of A2 (loc) and B0/B1 (W2) done

    // overwrite A2 with preds2 (+b2*log2e); pre-issue pos chunks 0,1
#pragma unroll
    for (int p = 0; p < 2; ++p)
#pragma unroll
        for (int mi = 0; mi < 2; ++mi)
#pragma unroll
            for (int ni = 0; ni < 4; ++ni) {
                int row = wy * 32 + mi * 16 + g;
                int col = p * 64 + wx * 32 + ni * 8 + tig * 2;
                float bv0 = __ldg(b2 + col) * LOG2E, bv1 = __ldg(b2 + col + 1) * LOG2E;
                float2 lo = up2(pc[p][mi][ni][0]), hi = up2(pc[p][mi][ni][1]);
                *reinterpret_cast<uint32_t*>(sm + OFF_A2 + row * SKB + col * 2) =
                    ph2(lo.x + bv0, lo.y + bv1);
                *reinterpret_cast<uint32_t*>(sm + OFF_A2 + (row + 8) * SKB + col * 2) =
                    ph2(hi.x + bv0, hi.y + bv1);
            }
#pragma unroll
    for (int j = 0; j < 4; ++j) {         // chunk 0 -> buf0
        int idx = j * 256 + t, row = idx >> 4, piece = idx & 15;
        cpa16(sbase + OFF_B0 + row * SKB + piece * 16,
              g_posh + (size_t)row * FSTRIDE + l * CDIM + piece * 8);
    }
    CP_COMMIT();
#pragma unroll
    for (int j = 0; j < 4; ++j) {         // chunk 1 -> buf1
        int idx = j * 256 + t, row = idx >> 4, piece = idx & 15;
        cpa16(sbase + OFF_B0 + BBUF_SZ + row * SKB + piece * 16,
              g_posh + (size_t)(64 + row) * FSTRIDE + l * CDIM + piece * 8);
    }
    CP_COMMIT();

    // ---- Phase 2: 8 chunks, triple-buffered B, ONE sync per chunk ----
    float S1[4] = {0.f, 0.f, 0.f, 0.f};
    float S2[4] = {0.f, 0.f, 0.f, 0.f};
    float diagAcc = 0.f;

    int bufR = 0, bufW = 2;               // read buf = ch%3; write buf = (ch+2)%3
#pragma unroll 1
    for (int ch = 0; ch < 8; ++ch) {
        CP_WAIT(1);                       // chunk ch landed (ch+1 may be in flight)
        __syncthreads();                  // also covers A2/preds2 visibility (ch=0)

        if (ch < 6) {                     // prefetch chunk ch+2 -> buf[(ch+2)%3]
            const uint32_t dstB = sbase + OFF_B0 + bufW * BBUF_SZ;
#pragma unroll
            for (int j = 0; j < 4; ++j) {
                int idx = j * 256 + t, row = idx >> 4, piece = idx & 15;
                cpa16(dstB + row * SKB + piece * 16,
                      g_posh + (size_t)((ch + 2) * 64 + row) * FSTRIDE + l * CDIM + piece * 8);
            }
        }
        CP_COMMIT();                      // empty group when ch>=6

        const uint32_t sbB = sbase + OFF_B0 + bufR * BBUF_SZ;
        uint32_t c1[2][4][2], c2[2][4][2];
#pragma unroll
        for (int mi = 0; mi < 2; ++mi)
#pragma unroll
            for (int ni = 0; ni < 4; ++ni) {
                c1[mi][ni][0] = 0u; c1[mi][ni][1] = 0u;
                c2[mi][ni][0] = 0u; c2[mi][ni][1] = 0u;
            }

#pragma unroll
        for (int ks = 0; ks < 8; ++ks) {
            const int k0 = ks * 16;
            uint32_t a2f[2][4], b[4][2];
            uint4 f0 = pA1[ks * 32];              // A1 frags mi=0 (L1-resident)
            uint4 f1 = pA1[(8 + ks) * 32];        // mi=1
#pragma unroll
            for (int mi = 0; mi < 2; ++mi) {
                uint32_t off = (wy * 32 + mi * 16 + aRow) * SKB + (k0 + aKoff) * 2;
                LDSM4(a2f[mi][0], a2f[mi][1], a2f[mi][2], a2f[mi][3], sbA2 + off);
            }
#pragma unroll
            for (int nt = 0; nt < 2; ++nt) {
                uint32_t bd = sbB + (wx * 32 + nt * 16 + bRow) * SKB + (k0 + bKoff) * 2;
                LDSM4(b[nt * 2][0], b[nt * 2][1], b[nt * 2 + 1][0], b[nt * 2 + 1][1], bd);
            }
            uint32_t a1f0[4] = {f0.x, f0.y, f0.z, f0.w};
            uint32_t a1f1[4] = {f1.x, f1.y, f1.z, f1.w};
#pragma unroll
            for (int ni = 0; ni < 4; ++ni) {
                mma16h(c1[0][ni], a1f0, b[ni]);
                mma16h(c1[1][ni], a1f1, b[ni]);
                mma16h(c2[0][ni], a2f[0], b[ni]);
                mma16h(c2[1][ni], a2f[1], b[ni]);
            }
        }

        // epilogue: logits log2-scaled -> raw ex2
#pragma unroll
        for (int mi = 0; mi < 2; ++mi) {
            const int r0 = nb * 128 + wy * 32 + mi * 16 + g;
            const int r1 = r0 + 8;
#pragma unroll
            for (int ni = 0; ni < 4; ++ni) {
                const int col = ch * 64 + wx * 32 + ni * 8 + tig * 2;
                float2 v1lo = up2(c1[mi][ni][0]), v1hi = up2(c1[mi][ni][1]);
                float2 v2lo = up2(c2[mi][ni][0]), v2hi = up2(c2[mi][ni][1]);
                S1[mi * 2 + 0] += ex2f(v1lo.x) + ex2f(v1lo.y);
                S1[mi * 2 + 1] += ex2f(v1hi.x) + ex2f(v1hi.y);
                S2[mi * 2 + 0] += ex2f(v2lo.x) + ex2f(v2lo.y);
                S2[mi * 2 + 1] += ex2f(v2hi.x) + ex2f(v2hi.y);
                if (col     == r0) diagAcc += v1lo.x + v2lo.x;
                if (col + 1 == r0) diagAcc += v1lo.y + v2lo.y;
                if (col     == r1) diagAcc += v1hi.x + v2hi.x;
                if (col + 1 == r1) diagAcc += v1hi.y + v2hi.y;
            }
        }
        bufR = (bufR == 2) ? 0 : bufR + 1;
        bufW = (bufW == 2) ? 0 : bufW + 1;
    }

    // ---- Phase 3: reductions + fused finalize ----
#pragma unroll
    for (int slot = 0; slot < 4; ++slot) {
        float s1 = S1[slot], s2 = S2[slot];
        s1 += __shfl_xor_sync(0xffffffffu, s1, 1);
        s1 += __shfl_xor_sync(0xffffffffu, s1, 2);
        s2 += __shfl_xor_sync(0xffffffffu, s2, 1);
        s2 += __shfl_xor_sync(0xffffffffu, s2, 2);
        if (tig == 0) {
            int row = wy * 32 + (slot >> 1) * 16 + g + (slot & 1) * 8;
            atomicAdd(&rowS[row], s1);
            atomicAdd(&rowS[128 + row], s2);
        }
    }
    __syncthreads();

    float contrib = -diagAcc * LN2 + __logf(rowS[t]);
#pragma unroll
    for (int off = 16; off > 0; off >>= 1)
        contrib += __shfl_down_sync(0xffffffffu, contrib, off);
    if (lane == 0) wred[warp] = contrib;
    __syncthreads();
    if (t == 0) {
        float v = 0.f;
#pragma unroll
        for (int w = 0; w < 8; ++w) v += wred[w];
        atomicAdd(&g_acc, (double)v);
        __threadfence();
        unsigned fin = atomicAdd(&g_done, 1u);
        if (fin == (unsigned)(4 * LLOC - 1)) {
            out[0] = (float)(g_acc / (double)(LLOC * NTOK));
            g_done = 0;
            g_acc = 0.0;
        }
    }
}

extern "C" void kernel_launch(void* const* d_in, const int* in_sizes, int n_in,
                              void* d_out, int out_size) {
    const float* f_t      = (const float*)d_in[0];
    const float* fmap_t   = (const float*)d_in[1];
    const float* fmap_tp1 = (const float*)d_in[2];
    const float* W1       = (const float*)d_in[3];
    const float* b1       = (const float*)d_in[4];
    const float* W2       = (const float*)d_in[5];
    const float* b2       = (const float*)d_in[6];
    float* out = (float*)d_out;

    cudaFuncSetAttribute(setup_k, cudaFuncAttributeMaxDynamicSharedMemorySize, P_SMEM);
    cudaFuncSetAttribute(main_k, cudaFuncAttributeMaxDynamicSharedMemorySize, SMEM_TOTAL);

    setup_k<<<8 + CONVB, 256, P_SMEM>>>(f_t, W1, b1, fmap_tp1);
    dim3 grid(NTOK / 128, LLOC);         // (4, 144)
    main_k<<<grid, 256, SMEM_TOTAL>>>(fmap_t, W2, b2, out);
}